// round 5
// baseline (speedup 1.0000x reference)
#include <cuda_runtime.h>
#include <cuda_bf16.h>
#include <cstdint>
#include <math.h>

#define SEQQ 2048
#define SEQK 2048
#define NB   4
#define NH   16
#define HD   64
#define DIMQ 1024
#define QK_SCALE 0.125f
#define SST  72    // K/Q/proj smem row stride (bf16 elems) = 144B
#define SSTV 136   // V smem row stride (bf16 elems) = 272B

// ---------------- static device scratch ----------------
__device__ uint32_t g_S[(size_t)NB * NH * SEQQ * SEQK];     // packed bf16 hi|lo exp-scores
__device__ float    g_rowsum[(size_t)SEQQ * NB * NH];
__device__ unsigned short g_Kh[(size_t)NB * NH * SEQK * HD];  // K hi plane [bh][j][d]
__device__ unsigned short g_Kl[(size_t)NB * NH * SEQK * HD];
__device__ unsigned short g_Vh[(size_t)NB * NH * HD * SEQK];  // V^T hi plane [bh][d][j]
__device__ unsigned short g_Vl[(size_t)NB * NH * HD * SEQK];
__device__ unsigned short g_xh[(size_t)SEQQ * NB * DIMQ];     // x hi plane [row][col]
__device__ unsigned short g_xl[(size_t)SEQQ * NB * DIMQ];
__device__ unsigned short g_Wh[(size_t)DIMQ * DIMQ];
__device__ unsigned short g_Wl[(size_t)DIMQ * DIMQ];
__device__ unsigned char g_M[NB][(size_t)SEQQ * SEQK];

// ---------------- helpers ----------------
__device__ __forceinline__ uint32_t smem_u32(const void* p) {
    uint32_t a;
    asm("{ .reg .u64 t; cvta.to.shared.u64 t, %1; cvt.u32.u64 %0, t; }" : "=r"(a) : "l"(p));
    return a;
}
__device__ __forceinline__ void cp16(uint32_t dst, const void* src) {
    asm volatile("cp.async.cg.shared.global [%0], [%1], 16;" :: "r"(dst), "l"(src));
}
#define CP_COMMIT() asm volatile("cp.async.commit_group;" ::: "memory")
#define CP_WAIT(n)  asm volatile("cp.async.wait_group %0;" :: "n"(n) : "memory")

__device__ __forceinline__ void ldsm4(uint32_t r[4], uint32_t addr) {
    asm volatile("ldmatrix.sync.aligned.m8n8.x4.shared.b16 {%0,%1,%2,%3}, [%4];"
                 : "=r"(r[0]), "=r"(r[1]), "=r"(r[2]), "=r"(r[3]) : "r"(addr));
}
__device__ __forceinline__ void mma_bf16(float* c, const uint32_t* a, uint32_t b0, uint32_t b1) {
    asm volatile("mma.sync.aligned.m16n8k16.row.col.f32.bf16.bf16.f32 "
                 "{%0,%1,%2,%3},{%4,%5,%6,%7},{%8,%9},{%0,%1,%2,%3};"
                 : "+f"(c[0]), "+f"(c[1]), "+f"(c[2]), "+f"(c[3])
                 : "r"(a[0]), "r"(a[1]), "r"(a[2]), "r"(a[3]), "r"(b0), "r"(b1));
}
// A fragment (m16 x k16); boff = byte offset of tile base in smem
__device__ __forceinline__ void lda(uint32_t r[4], uint32_t sb, int boff, int stride,
                                    int m0, int k0, int lane) {
    int row = m0 + (lane & 15);
    int col = k0 + ((lane >> 4) << 3);
    ldsm4(r, sb + (uint32_t)boff + (uint32_t)(row * stride + col) * 2);
}
__device__ __forceinline__ void ldb(uint32_t r[4], uint32_t sb, int boff, int stride,
                                    int n0, int k0, int lane) {
    int row = n0 + (lane & 7) + ((lane >> 4) << 3);
    int col = k0 + (((lane >> 3) & 1) << 3);
    ldsm4(r, sb + (uint32_t)boff + (uint32_t)(row * stride + col) * 2);
}

__device__ __forceinline__ float unpack_split(uint32_t u) {
    return __bfloat162float(__ushort_as_bfloat16((unsigned short)(u & 0xFFFF))) +
           __bfloat162float(__ushort_as_bfloat16((unsigned short)(u >> 16)));
}
__device__ __forceinline__ void split2(float e0, float e1, uint32_t& hw, uint32_t& lw) {
    __nv_bfloat162 hp = __floats2bfloat162_rn(e0, e1);
    float l0 = e0 - __bfloat162float(hp.x);
    float l1 = e1 - __bfloat162float(hp.y);
    __nv_bfloat162 lp = __floats2bfloat162_rn(l0, l1);
    hw = *(uint32_t*)&hp;
    lw = *(uint32_t*)&lp;
}
__device__ __forceinline__ void split4(float4 v, uint2& hw, uint2& lw) {
    split2(v.x, v.y, hw.x, lw.x);
    split2(v.z, v.w, hw.y, lw.y);
}

// ---- k_attn smem layout (bytes); 2 stages + resident Q ----
#define AT_STAGE 71680
#define AT_K_HI 0
#define AT_K_LO 18432
#define AT_V_HI 36864
#define AT_V_LO 54272
#define AT_Q_HI 143360
#define AT_Q_LO 161792
#define AT_SMEM 180224

// ---- k_proj smem layout ----
#define PJ_STAGE 73728
#define PJ_A_HI 0
#define PJ_A_LO 18432
#define PJ_B_HI 36864
#define PJ_B_LO 55296
#define PJ_SMEM 147456

// ---------------------------------------------------------------------------
__global__ __launch_bounds__(256) void k_mask(const int* __restrict__ mask) {
    size_t idx = (size_t)blockIdx.x * 256 + threadIdx.x;
    int4 m = ((const int4*)mask)[idx];
    g_M[0][idx] = (m.x != 0);
    g_M[1][idx] = (m.y != 0);
    g_M[2][idx] = (m.z != 0);
    g_M[3][idx] = (m.w != 0);
}

// ---------------------------------------------------------------------------
// K prep: split fp32 K -> g_Kh/g_Kl [bh][j][64]
// ---------------------------------------------------------------------------
__global__ __launch_bounds__(256) void k_kt(const float* __restrict__ k) {
    int bh = blockIdx.x, jt = blockIdx.y;
    int b = bh >> 4, h = bh & 15;
    int t = threadIdx.x;
    const float* kbase = k + b * DIMQ + h * HD;
    #pragma unroll
    for (int r = 0; r < 4; r++) {
        int idx = t + r * 256;
        int row = idx >> 4, d4 = idx & 15;
        float4 v = *(const float4*)(kbase + (size_t)(jt * 64 + row) * (NB * DIMQ) + d4 * 4);
        uint2 hw, lw; split4(v, hw, lw);
        size_t o = ((size_t)bh * SEQK + jt * 64 + row) * HD + d4 * 4;
        *(uint2*)(g_Kh + o) = hw;
        *(uint2*)(g_Kl + o) = lw;
    }
}

// ---------------------------------------------------------------------------
// V prep: transpose + split -> g_Vh/g_Vl [bh][d][j]
// ---------------------------------------------------------------------------
__global__ __launch_bounds__(256) void k_vt(const float* __restrict__ v) {
    int bh = blockIdx.x, jt = blockIdx.y;
    int b = bh >> 4, h = bh & 15;
    __shared__ float T[64][68];
    int t = threadIdx.x;
    #pragma unroll
    for (int r = 0; r < 4; r++) {
        int idx = t + r * 256;
        int j = idx >> 4, d4 = idx & 15;
        float4 vv = *(const float4*)(v + (size_t)(jt * 64 + j) * (NB * DIMQ) + b * DIMQ + h * HD + d4 * 4);
        T[j][d4 * 4 + 0] = vv.x; T[j][d4 * 4 + 1] = vv.y;
        T[j][d4 * 4 + 2] = vv.z; T[j][d4 * 4 + 3] = vv.w;
    }
    __syncthreads();
    #pragma unroll
    for (int r = 0; r < 4; r++) {
        int idx = t + r * 256;
        int d = idx >> 4, j4 = idx & 15;
        float4 vv;
        vv.x = T[j4 * 4 + 0][d]; vv.y = T[j4 * 4 + 1][d];
        vv.z = T[j4 * 4 + 2][d]; vv.w = T[j4 * 4 + 3][d];
        uint2 hw, lw; split4(vv, hw, lw);
        size_t o = ((size_t)bh * HD + d) * SEQK + jt * 64 + j4 * 4;
        *(uint2*)(g_Vh + o) = hw;
        *(uint2*)(g_Vl + o) = lw;
    }
}

// ---------------------------------------------------------------------------
// W prep: split fp32 W -> g_Wh/g_Wl
// ---------------------------------------------------------------------------
__global__ __launch_bounds__(256) void k_wt(const float* __restrict__ W) {
    size_t idx = ((size_t)blockIdx.x * 256 + threadIdx.x) * 4;
    float4 v = *(const float4*)(W + idx);
    uint2 hw, lw; split4(v, hw, lw);
    *(uint2*)(g_Wh + idx) = hw;
    *(uint2*)(g_Wl + idx) = lw;
}

// ---------------------------------------------------------------------------
// Fused attention with cp.async double-buffered K/V chunks.
// ---------------------------------------------------------------------------
__device__ __forceinline__ void attn_issue(uint32_t sb, int s, int bh, int kt, int t) {
    uint32_t base = sb + s * AT_STAGE;
    const unsigned short* kh = g_Kh + (size_t)bh * SEQK * HD;
    const unsigned short* kl = g_Kl + (size_t)bh * SEQK * HD;
    const unsigned short* vh = g_Vh + (size_t)bh * HD * SEQK;
    const unsigned short* vl = g_Vl + (size_t)bh * HD * SEQK;
    #pragma unroll
    for (int r = 0; r < 4; r++) {
        int id = t + r * 256;
        int row = id >> 3, seg = id & 7;   // 128 rows x 8 chunks
        size_t so = (size_t)(kt * 128 + row) * HD + seg * 8;
        cp16(base + AT_K_HI + row * 144 + seg * 16, kh + so);
        cp16(base + AT_K_LO + row * 144 + seg * 16, kl + so);
    }
    #pragma unroll
    for (int r = 0; r < 4; r++) {
        int id = t + r * 256;
        int row = id >> 4, seg = id & 15;  // 64 rows x 16 chunks
        size_t so = (size_t)row * SEQK + kt * 128 + seg * 8;
        cp16(base + AT_V_HI + row * 272 + seg * 16, vh + so);
        cp16(base + AT_V_LO + row * 272 + seg * 16, vl + so);
    }
}

__global__ __launch_bounds__(256) void k_attn(const float* __restrict__ q) {
    extern __shared__ char smem[];
    uint32_t sb = smem_u32(smem);
    int t = threadIdx.x, lane = t & 31, wid = t >> 5;
    int qt = blockIdx.x, bh = blockIdx.y;
    int b = bh >> 4, h = bh & 15;

    const float* qbase = q + b * DIMQ + h * HD;

    // resident Q tile [128 x 64], scaled + split
    #pragma unroll
    for (int r = 0; r < 8; r++) {
        int idx = t + r * 256;
        int row = idx >> 4, c4 = idx & 15;
        float4 v = *(const float4*)(qbase + (size_t)(qt * 128 + row) * (NB * DIMQ) + c4 * 4);
        v.x *= QK_SCALE; v.y *= QK_SCALE; v.z *= QK_SCALE; v.w *= QK_SCALE;
        uint2 hw, lw; split4(v, hw, lw);
        *(uint2*)(smem + AT_Q_HI + (size_t)(row * SST + c4 * 4) * 2) = hw;
        *(uint2*)(smem + AT_Q_LO + (size_t)(row * SST + c4 * 4) * 2) = lw;
    }

    attn_issue(sb, 0, bh, 0, t);
    CP_COMMIT();

    int r0 = wid * 16 + (lane >> 2);
    int gi0 = qt * 128 + r0;
    const unsigned char* mrow0 = g_M[b] + (size_t)gi0 * SEQK;
    const unsigned char* mrow1 = mrow0 + (size_t)8 * SEQK;
    uint32_t* srow0 = g_S + ((size_t)bh * SEQQ + gi0) * SEQK;
    uint32_t* srow1 = srow0 + (size_t)8 * SEQK;

    float oacc[8][4] = {};
    float rsum0 = 0.f, rsum1 = 0.f;

    for (int kt = 0; kt < 16; kt++) {
        if (kt < 15) { attn_issue(sb, (kt + 1) & 1, bh, kt + 1, t); CP_COMMIT(); }
        if (kt < 15) { CP_WAIT(1); } else { CP_WAIT(0); }
        __syncthreads();

        uint32_t stg = (uint32_t)((kt & 1) * AT_STAGE);

        // ---- MMA1: S(16x128) = Q(16x64) . K^T ----
        float cf[16][4] = {};
        #pragma unroll
        for (int ks = 0; ks < 4; ks++) {
            int k0 = ks * 16;
            uint32_t ah[4], al[4];
            lda(ah, sb, AT_Q_HI, SST, wid * 16, k0, lane);
            lda(al, sb, AT_Q_LO, SST, wid * 16, k0, lane);
            #pragma unroll
            for (int p = 0; p < 8; p++) {
                uint32_t bhf[4], blf[4];
                ldb(bhf, sb, stg + AT_K_HI, SST, p * 16, k0, lane);
                ldb(blf, sb, stg + AT_K_LO, SST, p * 16, k0, lane);
                #pragma unroll
                for (int qq = 0; qq < 2; qq++) {
                    int nf = p * 2 + qq;
                    mma_bf16(cf[nf], ah, bhf[qq * 2], bhf[qq * 2 + 1]);
                    mma_bf16(cf[nf], ah, blf[qq * 2], blf[qq * 2 + 1]);
                    mma_bf16(cf[nf], al, bhf[qq * 2], bhf[qq * 2 + 1]);
                }
            }
        }

        // ---- epilogue: exp*mask, split, store S packed, rowsum ----
        uint32_t shw[16][2], slw[16][2];
        #pragma unroll
        for (int nf = 0; nf < 16; nf++) {
            int jj = kt * 128 + nf * 8 + (lane & 3) * 2;
            unsigned short m0 = *(const unsigned short*)(mrow0 + jj);
            unsigned short m1 = *(const unsigned short*)(mrow1 + jj);
            float e00 = __expf(cf[nf][0]) * (float)(m0 & 0xFF);
            float e01 = __expf(cf[nf][1]) * (float)(m0 >> 8);
            float e10 = __expf(cf[nf][2]) * (float)(m1 & 0xFF);
            float e11 = __expf(cf[nf][3]) * (float)(m1 >> 8);
            rsum0 += e00 + e01;
            rsum1 += e10 + e11;
            split2(e00, e01, shw[nf][0], slw[nf][0]);
            split2(e10, e11, shw[nf][1], slw[nf][1]);
            uint2 w0, w1;
            w0.x = __byte_perm(shw[nf][0], slw[nf][0], 0x5410);
            w0.y = __byte_perm(shw[nf][0], slw[nf][0], 0x7632);
            w1.x = __byte_perm(shw[nf][1], slw[nf][1], 0x5410);
            w1.y = __byte_perm(shw[nf][1], slw[nf][1], 0x7632);
            *(uint2*)(srow0 + jj) = w0;
            *(uint2*)(srow1 + jj) = w1;
        }

        // ---- MMA2: O(16x64) += S(16x128) . V ----
        #pragma unroll
        for (int s = 0; s < 8; s++) {
            uint32_t ah2[4] = { shw[2 * s][0], shw[2 * s][1], shw[2 * s + 1][0], shw[2 * s + 1][1] };
            uint32_t al2[4] = { slw[2 * s][0], slw[2 * s][1], slw[2 * s + 1][0], slw[2 * s + 1][1] };
            int k0 = s * 16;
            #pragma unroll
            for (int p = 0; p < 4; p++) {
                uint32_t bhf[4], blf[4];
                ldb(bhf, sb, stg + AT_V_HI, SSTV, p * 16, k0, lane);
                ldb(blf, sb, stg + AT_V_LO, SSTV, p * 16, k0, lane);
                #pragma unroll
                for (int qq = 0; qq < 2; qq++) {
                    int nf = p * 2 + qq;
                    mma_bf16(oacc[nf], ah2, bhf[qq * 2], bhf[qq * 2 + 1]);
                    mma_bf16(oacc[nf], ah2, blf[qq * 2], blf[qq * 2 + 1]);
                    mma_bf16(oacc[nf], al2, bhf[qq * 2], bhf[qq * 2 + 1]);
                }
            }
        }
        __syncthreads();
    }

    rsum0 += __shfl_xor_sync(0xffffffffu, rsum0, 1);
    rsum0 += __shfl_xor_sync(0xffffffffu, rsum0, 2);
    rsum1 += __shfl_xor_sync(0xffffffffu, rsum1, 1);
    rsum1 += __shfl_xor_sync(0xffffffffu, rsum1, 2);
    if ((lane & 3) == 0) {
        g_rowsum[(size_t)gi0 * (NB * NH) + bh] = rsum0;
        g_rowsum[(size_t)(gi0 + 8) * (NB * NH) + bh] = rsum1;
    }
    float rinv0 = 1.0f / rsum0, rinv1 = 1.0f / rsum1;

    size_t xr0 = (size_t)(gi0 * NB + b) * DIMQ + h * HD;
    size_t xr1 = (size_t)((gi0 + 8) * NB + b) * DIMQ + h * HD;
    #pragma unroll
    for (int nf = 0; nf < 8; nf++) {
        int dd = nf * 8 + (lane & 3) * 2;
        uint32_t h0, l0, h1, l1;
        split2(oacc[nf][0] * rinv0, oacc[nf][1] * rinv0, h0, l0);
        split2(oacc[nf][2] * rinv1, oacc[nf][3] * rinv1, h1, l1);
        *(uint32_t*)(g_xh + xr0 + dd) = h0;
        *(uint32_t*)(g_xl + xr0 + dd) = l0;
        *(uint32_t*)(g_xh + xr1 + dd) = h1;
        *(uint32_t*)(g_xl + xr1 + dd) = l1;
    }
}

// ---------------------------------------------------------------------------
// Projection with cp.async double buffering.
// ---------------------------------------------------------------------------
__device__ __forceinline__ void proj_issue(uint32_t sb, int s, int rt, int nt, int mt, int t) {
    uint32_t base = sb + s * PJ_STAGE;
    #pragma unroll
    for (int r = 0; r < 4; r++) {
        int id = t + r * 256;
        int row = id >> 3, seg = id & 7;
        size_t ao = (size_t)(rt * 128 + row) * DIMQ + mt * 64 + seg * 8;
        size_t bo = (size_t)(nt * 128 + row) * DIMQ + mt * 64 + seg * 8;
        cp16(base + PJ_A_HI + row * 144 + seg * 16, g_xh + ao);
        cp16(base + PJ_A_LO + row * 144 + seg * 16, g_xl + ao);
        cp16(base + PJ_B_HI + row * 144 + seg * 16, g_Wh + bo);
        cp16(base + PJ_B_LO + row * 144 + seg * 16, g_Wl + bo);
    }
}

__global__ __launch_bounds__(256) void k_proj(const float* __restrict__ bias,
                                              float* __restrict__ out) {
    extern __shared__ char smem[];
    uint32_t sb = smem_u32(smem);
    int t = threadIdx.x, lane = t & 31, wid = t >> 5;
    int wm = wid >> 1, wn = wid & 1;
    int rt = blockIdx.x, nt = blockIdx.y;

    float acc[2][8][4] = {};

    proj_issue(sb, 0, rt, nt, 0, t);
    CP_COMMIT();

    for (int mt = 0; mt < 16; mt++) {
        if (mt < 15) { proj_issue(sb, (mt + 1) & 1, rt, nt, mt + 1, t); CP_COMMIT(); }
        if (mt < 15) { CP_WAIT(1); } else { CP_WAIT(0); }
        __syncthreads();

        uint32_t stg = (uint32_t)((mt & 1) * PJ_STAGE);

        #pragma unroll
        for (int ks = 0; ks < 4; ks++) {
            int k0 = ks * 16;
            uint32_t ah[2][4], al[2][4];
            lda(ah[0], sb, stg + PJ_A_HI, SST, wm * 32, k0, lane);
            lda(ah[1], sb, stg + PJ_A_HI, SST, wm * 32 + 16, k0, lane);
            lda(al[0], sb, stg + PJ_A_LO, SST, wm * 32, k0, lane);
            lda(al[1], sb, stg + PJ_A_LO, SST, wm * 32 + 16, k0, lane);
            #pragma unroll
            for (int p = 0; p < 4; p++) {
                uint32_t bhf[4], blf[4];
                ldb(bhf, sb, stg + PJ_B_HI, SST, wn * 64 + p * 16, k0, lane);
                ldb(blf, sb, stg + PJ_B_LO, SST, wn * 64 + p * 16, k0, lane);
                #pragma unroll
                for (int qq = 0; qq < 2; qq++) {
                    int nf = p * 2 + qq;
                    #pragma unroll
                    for (int mf = 0; mf < 2; mf++) {
                        mma_bf16(acc[mf][nf], ah[mf], bhf[qq * 2], bhf[qq * 2 + 1]);
                        mma_bf16(acc[mf][nf], ah[mf], blf[qq * 2], blf[qq * 2 + 1]);
                        mma_bf16(acc[mf][nf], al[mf], bhf[qq * 2], bhf[qq * 2 + 1]);
                    }
                }
            }
        }
        __syncthreads();
    }

    #pragma unroll
    for (int mf = 0; mf < 2; mf++)
        #pragma unroll
        for (int r8 = 0; r8 < 2; r8++) {
            int row = rt * 128 + wm * 32 + mf * 16 + r8 * 8 + (lane >> 2);
            float* orow = out + (size_t)row * DIMQ + nt * 128 + wn * 64;
            const float* brow = bias + nt * 128 + wn * 64;
            #pragma unroll
            for (int nf = 0; nf < 8; nf++) {
                int cc = nf * 8 + (lane & 3) * 2;
                float2 o;
                o.x = acc[mf][nf][r8 * 2 + 0] + brow[cc];
                o.y = acc[mf][nf][r8 * 2 + 1] + brow[cc + 1];
                *(float2*)(orow + cc) = o;
            }
        }
}

// ---------------------------------------------------------------------------
// attn writer: gather-transpose, normalize
// ---------------------------------------------------------------------------
__global__ __launch_bounds__(256) void k_attnT(float* __restrict__ attn) {
    int i = blockIdx.x, jt = blockIdx.y;
    __shared__ float T[64][68];
    __shared__ float rinv_s[64];
    int t = threadIdx.x;
    if (t < 64) rinv_s[t] = 1.0f / g_rowsum[(size_t)i * 64 + t];
    {
        int c = t >> 2, l4 = t & 3;
        const uint32_t* src = g_S + ((size_t)c * SEQQ + i) * SEQK + jt * 64 + l4 * 16;
        #pragma unroll
        for (int r = 0; r < 4; r++) {
            uint4 pv = *(const uint4*)(src + r * 4);
            int j = l4 * 16 + r * 4;
            T[j + 0][c] = unpack_split(pv.x); T[j + 1][c] = unpack_split(pv.y);
            T[j + 2][c] = unpack_split(pv.z); T[j + 3][c] = unpack_split(pv.w);
        }
    }
    __syncthreads();
    {
        int c0 = (t & 15) * 4;
        int jb = t >> 4;
        #pragma unroll
        for (int r = 0; r < 4; r++) {
            int j = jb + r * 16;
            float4 o;
            o.x = T[j][c0 + 0] * rinv_s[c0 + 0];
            o.y = T[j][c0 + 1] * rinv_s[c0 + 1];
            o.z = T[j][c0 + 2] * rinv_s[c0 + 2];
            o.w = T[j][c0 + 3] * rinv_s[c0 + 3];
            *(float4*)(attn + ((size_t)i * SEQK + jt * 64 + j) * 64 + c0) = o;
        }
    }
}

// ---------------------------------------------------------------------------
extern "C" void kernel_launch(void* const* d_in, const int* in_sizes, int n_in,
                              void* d_out, int out_size) {
    const float* q    = (const float*)d_in[0];
    const float* k    = (const float*)d_in[1];
    const float* v    = (const float*)d_in[2];
    const int*   mask = (const int*)d_in[3];
    const float* W    = (const float*)d_in[4];
    const float* bias = (const float*)d_in[5];
    float* out = (float*)d_out;

    cudaFuncSetAttribute(k_attn, cudaFuncAttributeMaxDynamicSharedMemorySize, AT_SMEM);
    cudaFuncSetAttribute(k_proj, cudaFuncAttributeMaxDynamicSharedMemorySize, PJ_SMEM);

    k_mask<<<(SEQQ * SEQK) / 256, 256>>>(mask);
    k_kt<<<dim3(NB * NH, SEQK / 64), 256>>>(k);
    k_vt<<<dim3(NB * NH, SEQK / 64), 256>>>(v);
    k_wt<<<(DIMQ * DIMQ) / 1024, 256>>>(W);
    k_attn<<<dim3(SEQQ / 128, NB * NH), 256, AT_SMEM>>>(q);
    k_proj<<<dim3(SEQQ * NB / 128, DIMQ / 128), 256, PJ_SMEM>>>(bias, out);

    const long long OUT_ELEMS  = (long long)SEQQ * NB * DIMQ;
    const long long ATTN_ELEMS = (long long)SEQQ * SEQK * NB * NH;
    if ((long long)out_size >= OUT_ELEMS + ATTN_ELEMS) {
        float* attn = out + OUT_ELEMS;
        k_attnT<<<dim3(SEQQ, SEQK / 64), 256>>>(attn);
    }
}

// round 6
// speedup vs baseline: 1.5022x; 1.5022x over previous
#include <cuda_runtime.h>
#include <cuda_bf16.h>
#include <cstdint>
#include <math.h>

#define SEQQ 2048
#define SEQK 2048
#define NB   4
#define NH   16
#define HD   64
#define DIMQ 1024
#define QK_SCALE 0.125f
#define SST  72    // K/Q/proj smem row stride (bf16 elems) = 144B
#define SSTV 136   // V smem row stride (bf16 elems) = 272B

// ---------------- static device scratch ----------------
__device__ uint32_t g_S[(size_t)NB * NH * SEQQ * SEQK];     // packed bf16 hi|lo exp-scores
__device__ float    g_rowsum[(size_t)SEQQ * NB * NH];
__device__ unsigned short g_Kh[(size_t)NB * NH * SEQK * HD];  // K hi plane [bh][j][d]
__device__ unsigned short g_Kl[(size_t)NB * NH * SEQK * HD];
__device__ unsigned short g_Vh[(size_t)NB * NH * HD * SEQK];  // V^T hi plane [bh][d][j]
__device__ unsigned short g_Vl[(size_t)NB * NH * HD * SEQK];
__device__ unsigned short g_xh[(size_t)SEQQ * NB * DIMQ];     // x hi plane [row][col]
__device__ unsigned short g_xl[(size_t)SEQQ * NB * DIMQ];
__device__ unsigned short g_Wh[(size_t)DIMQ * DIMQ];
__device__ unsigned short g_Wl[(size_t)DIMQ * DIMQ];
__device__ unsigned char g_M[NB][(size_t)SEQQ * SEQK];

// ---------------- helpers ----------------
__device__ __forceinline__ uint32_t smem_u32(const void* p) {
    uint32_t a;
    asm("{ .reg .u64 t; cvta.to.shared.u64 t, %1; cvt.u32.u64 %0, t; }" : "=r"(a) : "l"(p));
    return a;
}
__device__ __forceinline__ void cp16(uint32_t dst, const void* src) {
    asm volatile("cp.async.cg.shared.global [%0], [%1], 16;" :: "r"(dst), "l"(src));
}
#define CP_COMMIT() asm volatile("cp.async.commit_group;" ::: "memory")
#define CP_WAIT(n)  asm volatile("cp.async.wait_group %0;" :: "n"(n) : "memory")

__device__ __forceinline__ void ldsm4(uint32_t r[4], uint32_t addr) {
    asm volatile("ldmatrix.sync.aligned.m8n8.x4.shared.b16 {%0,%1,%2,%3}, [%4];"
                 : "=r"(r[0]), "=r"(r[1]), "=r"(r[2]), "=r"(r[3]) : "r"(addr));
}
__device__ __forceinline__ void mma_bf16(float* c, const uint32_t* a, uint32_t b0, uint32_t b1) {
    asm volatile("mma.sync.aligned.m16n8k16.row.col.f32.bf16.bf16.f32 "
                 "{%0,%1,%2,%3},{%4,%5,%6,%7},{%8,%9},{%0,%1,%2,%3};"
                 : "+f"(c[0]), "+f"(c[1]), "+f"(c[2]), "+f"(c[3])
                 : "r"(a[0]), "r"(a[1]), "r"(a[2]), "r"(a[3]), "r"(b0), "r"(b1));
}
// A fragment (m16 x k16); boff = byte offset of tile base in smem
__device__ __forceinline__ void lda(uint32_t r[4], uint32_t sb, int boff, int stride,
                                    int m0, int k0, int lane) {
    int row = m0 + (lane & 15);
    int col = k0 + ((lane >> 4) << 3);
    ldsm4(r, sb + (uint32_t)boff + (uint32_t)(row * stride + col) * 2);
}
__device__ __forceinline__ void ldb(uint32_t r[4], uint32_t sb, int boff, int stride,
                                    int n0, int k0, int lane) {
    int row = n0 + (lane & 7) + ((lane >> 4) << 3);
    int col = k0 + (((lane >> 3) & 1) << 3);
    ldsm4(r, sb + (uint32_t)boff + (uint32_t)(row * stride + col) * 2);
}

__device__ __forceinline__ float unpack_split(uint32_t u) {
    return __bfloat162float(__ushort_as_bfloat16((unsigned short)(u & 0xFFFF))) +
           __bfloat162float(__ushort_as_bfloat16((unsigned short)(u >> 16)));
}
__device__ __forceinline__ void split2(float e0, float e1, uint32_t& hw, uint32_t& lw) {
    __nv_bfloat162 hp = __floats2bfloat162_rn(e0, e1);
    float l0 = e0 - __bfloat162float(hp.x);
    float l1 = e1 - __bfloat162float(hp.y);
    __nv_bfloat162 lp = __floats2bfloat162_rn(l0, l1);
    hw = *(uint32_t*)&hp;
    lw = *(uint32_t*)&lp;
}
__device__ __forceinline__ void split4(float4 v, uint2& hw, uint2& lw) {
    split2(v.x, v.y, hw.x, lw.x);
    split2(v.z, v.w, hw.y, lw.y);
}

// ---- k_attn smem layout (bytes); 2 stages + resident Q ----
#define AT_STAGE 71680
#define AT_K_HI 0
#define AT_K_LO 18432
#define AT_V_HI 36864
#define AT_V_LO 54272
#define AT_Q_HI 143360
#define AT_Q_LO 161792
#define AT_SMEM 180224

// ---- k_proj smem layout ----
#define PJ_STAGE 73728
#define PJ_A_HI 0
#define PJ_A_LO 18432
#define PJ_B_HI 36864
#define PJ_B_LO 55296
#define PJ_SMEM 147456

// ---------------------------------------------------------------------------
__global__ __launch_bounds__(256) void k_mask(const int* __restrict__ mask) {
    size_t idx = (size_t)blockIdx.x * 256 + threadIdx.x;
    int4 m = ((const int4*)mask)[idx];
    g_M[0][idx] = (m.x != 0);
    g_M[1][idx] = (m.y != 0);
    g_M[2][idx] = (m.z != 0);
    g_M[3][idx] = (m.w != 0);
}

// ---------------------------------------------------------------------------
// K prep: split fp32 K -> g_Kh/g_Kl [bh][j][64]
// ---------------------------------------------------------------------------
__global__ __launch_bounds__(256) void k_kt(const float* __restrict__ k) {
    int bh = blockIdx.x, jt = blockIdx.y;
    int b = bh >> 4, h = bh & 15;
    int t = threadIdx.x;
    const float* kbase = k + b * DIMQ + h * HD;
    #pragma unroll
    for (int r = 0; r < 4; r++) {
        int idx = t + r * 256;
        int row = idx >> 4, d4 = idx & 15;
        float4 v = *(const float4*)(kbase + (size_t)(jt * 64 + row) * (NB * DIMQ) + d4 * 4);
        uint2 hw, lw; split4(v, hw, lw);
        size_t o = ((size_t)bh * SEQK + jt * 64 + row) * HD + d4 * 4;
        *(uint2*)(g_Kh + o) = hw;
        *(uint2*)(g_Kl + o) = lw;
    }
}

// ---------------------------------------------------------------------------
// V prep: transpose + split -> g_Vh/g_Vl [bh][d][j]
// ---------------------------------------------------------------------------
__global__ __launch_bounds__(256) void k_vt(const float* __restrict__ v) {
    int bh = blockIdx.x, jt = blockIdx.y;
    int b = bh >> 4, h = bh & 15;
    __shared__ float T[64][68];
    int t = threadIdx.x;
    #pragma unroll
    for (int r = 0; r < 4; r++) {
        int idx = t + r * 256;
        int j = idx >> 4, d4 = idx & 15;
        float4 vv = *(const float4*)(v + (size_t)(jt * 64 + j) * (NB * DIMQ) + b * DIMQ + h * HD + d4 * 4);
        T[j][d4 * 4 + 0] = vv.x; T[j][d4 * 4 + 1] = vv.y;
        T[j][d4 * 4 + 2] = vv.z; T[j][d4 * 4 + 3] = vv.w;
    }
    __syncthreads();
    #pragma unroll
    for (int r = 0; r < 4; r++) {
        int idx = t + r * 256;
        int d = idx >> 4, j4 = idx & 15;
        float4 vv;
        vv.x = T[j4 * 4 + 0][d]; vv.y = T[j4 * 4 + 1][d];
        vv.z = T[j4 * 4 + 2][d]; vv.w = T[j4 * 4 + 3][d];
        uint2 hw, lw; split4(vv, hw, lw);
        size_t o = ((size_t)bh * HD + d) * SEQK + jt * 64 + j4 * 4;
        *(uint2*)(g_Vh + o) = hw;
        *(uint2*)(g_Vl + o) = lw;
    }
}

// ---------------------------------------------------------------------------
// W prep: split fp32 W -> g_Wh/g_Wl
// ---------------------------------------------------------------------------
__global__ __launch_bounds__(256) void k_wt(const float* __restrict__ W) {
    size_t idx = ((size_t)blockIdx.x * 256 + threadIdx.x) * 4;
    float4 v = *(const float4*)(W + idx);
    uint2 hw, lw; split4(v, hw, lw);
    *(uint2*)(g_Wh + idx) = hw;
    *(uint2*)(g_Wl + idx) = lw;
}

// ---------------------------------------------------------------------------
// Fused attention with cp.async double-buffered K/V chunks.
// ---------------------------------------------------------------------------
__device__ __forceinline__ void attn_issue(uint32_t sb, int s, int bh, int kt, int t) {
    uint32_t base = sb + s * AT_STAGE;
    const unsigned short* kh = g_Kh + (size_t)bh * SEQK * HD;
    const unsigned short* kl = g_Kl + (size_t)bh * SEQK * HD;
    const unsigned short* vh = g_Vh + (size_t)bh * HD * SEQK;
    const unsigned short* vl = g_Vl + (size_t)bh * HD * SEQK;
    #pragma unroll
    for (int r = 0; r < 4; r++) {
        int id = t + r * 256;
        int row = id >> 3, seg = id & 7;   // 128 rows x 8 chunks
        size_t so = (size_t)(kt * 128 + row) * HD + seg * 8;
        cp16(base + AT_K_HI + row * 144 + seg * 16, kh + so);
        cp16(base + AT_K_LO + row * 144 + seg * 16, kl + so);
    }
    #pragma unroll
    for (int r = 0; r < 4; r++) {
        int id = t + r * 256;
        int row = id >> 4, seg = id & 15;  // 64 rows x 16 chunks
        size_t so = (size_t)row * SEQK + kt * 128 + seg * 8;
        cp16(base + AT_V_HI + row * 272 + seg * 16, vh + so);
        cp16(base + AT_V_LO + row * 272 + seg * 16, vl + so);
    }
}

__global__ __launch_bounds__(256) void k_attn(const float* __restrict__ q) {
    extern __shared__ char smem[];
    uint32_t sb = smem_u32(smem);
    int t = threadIdx.x, lane = t & 31, wid = t >> 5;
    int qt = blockIdx.x, bh = blockIdx.y;
    int b = bh >> 4, h = bh & 15;

    const float* qbase = q + b * DIMQ + h * HD;

    // resident Q tile [128 x 64], scaled + split
    #pragma unroll
    for (int r = 0; r < 8; r++) {
        int idx = t + r * 256;
        int row = idx >> 4, c4 = idx & 15;
        float4 v = *(const float4*)(qbase + (size_t)(qt * 128 + row) * (NB * DIMQ) + c4 * 4);
        v.x *= QK_SCALE; v.y *= QK_SCALE; v.z *= QK_SCALE; v.w *= QK_SCALE;
        uint2 hw, lw; split4(v, hw, lw);
        *(uint2*)(smem + AT_Q_HI + (size_t)(row * SST + c4 * 4) * 2) = hw;
        *(uint2*)(smem + AT_Q_LO + (size_t)(row * SST + c4 * 4) * 2) = lw;
    }

    attn_issue(sb, 0, bh, 0, t);
    CP_COMMIT();

    int r0 = wid * 16 + (lane >> 2);
    int gi0 = qt * 128 + r0;
    const unsigned char* mrow0 = g_M[b] + (size_t)gi0 * SEQK;
    const unsigned char* mrow1 = mrow0 + (size_t)8 * SEQK;
    uint32_t* srow0 = g_S + ((size_t)bh * SEQQ + gi0) * SEQK;
    uint32_t* srow1 = srow0 + (size_t)8 * SEQK;

    float oacc[8][4] = {};
    float rsum0 = 0.f, rsum1 = 0.f;

    for (int kt = 0; kt < 16; kt++) {
        if (kt < 15) { attn_issue(sb, (kt + 1) & 1, bh, kt + 1, t); CP_COMMIT(); }
        if (kt < 15) { CP_WAIT(1); } else { CP_WAIT(0); }
        __syncthreads();

        uint32_t stg = (uint32_t)((kt & 1) * AT_STAGE);

        // ---- MMA1: S(16x128) = Q(16x64) . K^T ----
        float cf[16][4] = {};
        #pragma unroll
        for (int ks = 0; ks < 4; ks++) {
            int k0 = ks * 16;
            uint32_t ah[4], al[4];
            lda(ah, sb, AT_Q_HI, SST, wid * 16, k0, lane);
            lda(al, sb, AT_Q_LO, SST, wid * 16, k0, lane);
            #pragma unroll
            for (int p = 0; p < 8; p++) {
                uint32_t bhf[4], blf[4];
                ldb(bhf, sb, stg + AT_K_HI, SST, p * 16, k0, lane);
                ldb(blf, sb, stg + AT_K_LO, SST, p * 16, k0, lane);
                #pragma unroll
                for (int qq = 0; qq < 2; qq++) {
                    int nf = p * 2 + qq;
                    mma_bf16(cf[nf], ah, bhf[qq * 2], bhf[qq * 2 + 1]);
                    mma_bf16(cf[nf], ah, blf[qq * 2], blf[qq * 2 + 1]);
                    mma_bf16(cf[nf], al, bhf[qq * 2], bhf[qq * 2 + 1]);
                }
            }
        }

        // ---- epilogue: exp*mask, split, store S packed, rowsum ----
        uint32_t shw[16][2], slw[16][2];
        #pragma unroll
        for (int nf = 0; nf < 16; nf++) {
            int jj = kt * 128 + nf * 8 + (lane & 3) * 2;
            unsigned short m0 = *(const unsigned short*)(mrow0 + jj);
            unsigned short m1 = *(const unsigned short*)(mrow1 + jj);
            float e00 = __expf(cf[nf][0]) * (float)(m0 & 0xFF);
            float e01 = __expf(cf[nf][1]) * (float)(m0 >> 8);
            float e10 = __expf(cf[nf][2]) * (float)(m1 & 0xFF);
            float e11 = __expf(cf[nf][3]) * (float)(m1 >> 8);
            rsum0 += e00 + e01;
            rsum1 += e10 + e11;
            split2(e00, e01, shw[nf][0], slw[nf][0]);
            split2(e10, e11, shw[nf][1], slw[nf][1]);
            uint2 w0, w1;
            w0.x = __byte_perm(shw[nf][0], slw[nf][0], 0x5410);
            w0.y = __byte_perm(shw[nf][0], slw[nf][0], 0x7632);
            w1.x = __byte_perm(shw[nf][1], slw[nf][1], 0x5410);
            w1.y = __byte_perm(shw[nf][1], slw[nf][1], 0x7632);
            *(uint2*)(srow0 + jj) = w0;
            *(uint2*)(srow1 + jj) = w1;
        }

        // ---- MMA2: O(16x64) += S(16x128) . V ----
        #pragma unroll
        for (int s = 0; s < 8; s++) {
            uint32_t ah2[4] = { shw[2 * s][0], shw[2 * s][1], shw[2 * s + 1][0], shw[2 * s + 1][1] };
            uint32_t al2[4] = { slw[2 * s][0], slw[2 * s][1], slw[2 * s + 1][0], slw[2 * s + 1][1] };
            int k0 = s * 16;
            #pragma unroll
            for (int p = 0; p < 4; p++) {
                uint32_t bhf[4], blf[4];
                ldb(bhf, sb, stg + AT_V_HI, SSTV, p * 16, k0, lane);
                ldb(blf, sb, stg + AT_V_LO, SSTV, p * 16, k0, lane);
                #pragma unroll
                for (int qq = 0; qq < 2; qq++) {
                    int nf = p * 2 + qq;
                    mma_bf16(oacc[nf], ah2, bhf[qq * 2], bhf[qq * 2 + 1]);
                    mma_bf16(oacc[nf], ah2, blf[qq * 2], blf[qq * 2 + 1]);
                    mma_bf16(oacc[nf], al2, bhf[qq * 2], bhf[qq * 2 + 1]);
                }
            }
        }
        __syncthreads();
    }

    rsum0 += __shfl_xor_sync(0xffffffffu, rsum0, 1);
    rsum0 += __shfl_xor_sync(0xffffffffu, rsum0, 2);
    rsum1 += __shfl_xor_sync(0xffffffffu, rsum1, 1);
    rsum1 += __shfl_xor_sync(0xffffffffu, rsum1, 2);
    if ((lane & 3) == 0) {
        g_rowsum[(size_t)gi0 * (NB * NH) + bh] = rsum0;
        g_rowsum[(size_t)(gi0 + 8) * (NB * NH) + bh] = rsum1;
    }
    float rinv0 = 1.0f / rsum0, rinv1 = 1.0f / rsum1;

    size_t xr0 = (size_t)(gi0 * NB + b) * DIMQ + h * HD;
    size_t xr1 = (size_t)((gi0 + 8) * NB + b) * DIMQ + h * HD;
    #pragma unroll
    for (int nf = 0; nf < 8; nf++) {
        int dd = nf * 8 + (lane & 3) * 2;
        uint32_t h0, l0, h1, l1;
        split2(oacc[nf][0] * rinv0, oacc[nf][1] * rinv0, h0, l0);
        split2(oacc[nf][2] * rinv1, oacc[nf][3] * rinv1, h1, l1);
        *(uint32_t*)(g_xh + xr0 + dd) = h0;
        *(uint32_t*)(g_xl + xr0 + dd) = l0;
        *(uint32_t*)(g_xh + xr1 + dd) = h1;
        *(uint32_t*)(g_xl + xr1 + dd) = l1;
    }
}

// ---------------------------------------------------------------------------
// Projection with cp.async double buffering.
// ---------------------------------------------------------------------------
__device__ __forceinline__ void proj_issue(uint32_t sb, int s, int rt, int nt, int mt, int t) {
    uint32_t base = sb + s * PJ_STAGE;
    #pragma unroll
    for (int r = 0; r < 4; r++) {
        int id = t + r * 256;
        int row = id >> 3, seg = id & 7;
        size_t ao = (size_t)(rt * 128 + row) * DIMQ + mt * 64 + seg * 8;
        size_t bo = (size_t)(nt * 128 + row) * DIMQ + mt * 64 + seg * 8;
        cp16(base + PJ_A_HI + row * 144 + seg * 16, g_xh + ao);
        cp16(base + PJ_A_LO + row * 144 + seg * 16, g_xl + ao);
        cp16(base + PJ_B_HI + row * 144 + seg * 16, g_Wh + bo);
        cp16(base + PJ_B_LO + row * 144 + seg * 16, g_Wl + bo);
    }
}

__global__ __launch_bounds__(256) void k_proj(const float* __restrict__ bias,
                                              float* __restrict__ out) {
    extern __shared__ char smem[];
    uint32_t sb = smem_u32(smem);
    int t = threadIdx.x, lane = t & 31, wid = t >> 5;
    int wm = wid >> 1, wn = wid & 1;
    int rt = blockIdx.x, nt = blockIdx.y;

    float acc[2][8][4] = {};

    proj_issue(sb, 0, rt, nt, 0, t);
    CP_COMMIT();

    for (int mt = 0; mt < 16; mt++) {
        if (mt < 15) { proj_issue(sb, (mt + 1) & 1, rt, nt, mt + 1, t); CP_COMMIT(); }
        if (mt < 15) { CP_WAIT(1); } else { CP_WAIT(0); }
        __syncthreads();

        uint32_t stg = (uint32_t)((mt & 1) * PJ_STAGE);

        #pragma unroll
        for (int ks = 0; ks < 4; ks++) {
            int k0 = ks * 16;
            uint32_t ah[2][4], al[2][4];
            lda(ah[0], sb, stg + PJ_A_HI, SST, wm * 32, k0, lane);
            lda(ah[1], sb, stg + PJ_A_HI, SST, wm * 32 + 16, k0, lane);
            lda(al[0], sb, stg + PJ_A_LO, SST, wm * 32, k0, lane);
            lda(al[1], sb, stg + PJ_A_LO, SST, wm * 32 + 16, k0, lane);
            #pragma unroll
            for (int p = 0; p < 4; p++) {
                uint32_t bhf[4], blf[4];
                ldb(bhf, sb, stg + PJ_B_HI, SST, wn * 64 + p * 16, k0, lane);
                ldb(blf, sb, stg + PJ_B_LO, SST, wn * 64 + p * 16, k0, lane);
                #pragma unroll
                for (int qq = 0; qq < 2; qq++) {
                    int nf = p * 2 + qq;
                    #pragma unroll
                    for (int mf = 0; mf < 2; mf++) {
                        mma_bf16(acc[mf][nf], ah[mf], bhf[qq * 2], bhf[qq * 2 + 1]);
                        mma_bf16(acc[mf][nf], ah[mf], blf[qq * 2], blf[qq * 2 + 1]);
                        mma_bf16(acc[mf][nf], al[mf], bhf[qq * 2], bhf[qq * 2 + 1]);
                    }
                }
            }
        }
        __syncthreads();
    }

    #pragma unroll
    for (int mf = 0; mf < 2; mf++)
        #pragma unroll
        for (int r8 = 0; r8 < 2; r8++) {
            int row = rt * 128 + wm * 32 + mf * 16 + r8 * 8 + (lane >> 2);
            float* orow = out + (size_t)row * DIMQ + nt * 128 + wn * 64;
            const float* brow = bias + nt * 128 + wn * 64;
            #pragma unroll
            for (int nf = 0; nf < 8; nf++) {
                int cc = nf * 8 + (lane & 3) * 2;
                float2 o;
                o.x = acc[mf][nf][r8 * 2 + 0] + brow[cc];
                o.y = acc[mf][nf][r8 * 2 + 1] + brow[cc + 1];
                *(float2*)(orow + cc) = o;
            }
        }
}

// ---------------------------------------------------------------------------
// attn writer: gather-transpose, normalize
// ---------------------------------------------------------------------------
__global__ __launch_bounds__(256) void k_attnT(float* __restrict__ attn) {
    int i = blockIdx.x, jt = blockIdx.y;
    __shared__ float T[64][68];
    __shared__ float rinv_s[64];
    int t = threadIdx.x;
    if (t < 64) rinv_s[t] = 1.0f / g_rowsum[(size_t)i * 64 + t];
    {
        int c = t >> 2, l4 = t & 3;
        const uint32_t* src = g_S + ((size_t)c * SEQQ + i) * SEQK + jt * 64 + l4 * 16;
        #pragma unroll
        for (int r = 0; r < 4; r++) {
            uint4 pv = *(const uint4*)(src + r * 4);
            int j = l4 * 16 + r * 4;
            T[j + 0][c] = unpack_split(pv.x); T[j + 1][c] = unpack_split(pv.y);
            T[j + 2][c] = unpack_split(pv.z); T[j + 3][c] = unpack_split(pv.w);
        }
    }
    __syncthreads();
    {
        int c0 = (t & 15) * 4;
        int jb = t >> 4;
        #pragma unroll
        for (int r = 0; r < 4; r++) {
            int j = jb + r * 16;
            float4 o;
            o.x = T[j][c0 + 0] * rinv_s[c0 + 0];
            o.y = T[j][c0 + 1] * rinv_s[c0 + 1];
            o.z = T[j][c0 + 2] * rinv_s[c0 + 2];
            o.w = T[j][c0 + 3] * rinv_s[c0 + 3];
            *(float4*)(attn + ((size_t)i * SEQK + jt * 64 + j) * 64 + c0) = o;
        }
    }
}

// ---------------------------------------------------------------------------
extern "C" void kernel_launch(void* const* d_in, const int* in_sizes, int n_in,
                              void* d_out, int out_size) {
    const float* q    = (const float*)d_in[0];
    const float* k    = (const float*)d_in[1];
    const float* v    = (const float*)d_in[2];
    const int*   mask = (const int*)d_in[3];
    const float* W    = (const float*)d_in[4];
    const float* bias = (const float*)d_in[5];
    float* out = (float*)d_out;

    cudaFuncSetAttribute(k_attn, cudaFuncAttributeMaxDynamicSharedMemorySize, AT_SMEM);
    cudaFuncSetAttribute(k_proj, cudaFuncAttributeMaxDynamicSharedMemorySize, PJ_SMEM);

    k_mask<<<(SEQQ * SEQK) / 256, 256>>>(mask);
    k_kt<<<dim3(NB * NH, SEQK / 64), 256>>>(k);
    k_vt<<<dim3(NB * NH, SEQK / 64), 256>>>(v);
    k_wt<<<(DIMQ * DIMQ) / 1024, 256>>>(W);
    k_attn<<<dim3(SEQQ / 128, NB * NH), 256, AT_SMEM>>>(q);
    k_proj<<<dim3(SEQQ * NB / 128, DIMQ / 128), 256, PJ_SMEM>>>(bias, out);

    const long long OUT_ELEMS  = (long long)SEQQ * NB * DIMQ;
    const long long ATTN_ELEMS = (long long)SEQQ * SEQK * NB * NH;
    if ((long long)out_size >= OUT_ELEMS + ATTN_ELEMS) {
        float* attn = out + OUT_ELEMS;
        k_attnT<<<dim3(SEQQ, SEQK / 64), 256>>>(attn);
    }
}